// round 8
// baseline (speedup 1.0000x reference)
#include <cuda_runtime.h>
#include <cuda_bf16.h>
#include <cstdint>

// Fused GraphSAGE layer:
//   agg[n]  = (sum_s features[neigh[n,s]] + features[node[n]]) / (S+1)
//   out[n]  = l2norm(relu(agg[n] @ W + b))
//
// One block = 32 nodes, 512 threads, 2 blocks/SM.
// Phase 1: float4 gather with L2 evict-last cache-hint policy on the feature
//          table (keep hot rows resident); indices streamed with .cs.
// Phase 2: tf32 mma.sync m16n8k8, W staged via double-buffered smem tf32.
// Phase 3: bias/relu, shuffle row L2-norm, streaming (.cs) output store.

#define BM      32
#define DDIM    256
#define THREADS 512
#define MAX_S   40
#define ASTRIDE 260     // A tile row stride (words)
#define WSTRIDE 264     // W chunk row stride (words)

#define AS_BYTES  (BM * ASTRIDE * 4)
#define WS_BYTES  (2 * 8 * WSTRIDE * 4)
#define IDX_BYTES (BM * MAX_S * 4)
#define R2_BYTES  (WS_BYTES > IDX_BYTES ? WS_BYTES : IDX_BYTES)
#define SMEM_BYTES (AS_BYTES + R2_BYTES + 128)

__device__ __forceinline__ uint32_t f2tf32(float f) {
    uint32_t u;
    asm("cvt.rna.tf32.f32 %0, %1;" : "=r"(u) : "f"(f));
    return u;
}

// L2 evict-last policy (created once per thread)
__device__ __forceinline__ uint64_t mk_keep_policy() {
    uint64_t pol;
    asm("createpolicy.fractional.L2::evict_last.b64 %0, 1.0;" : "=l"(pol));
    return pol;
}

// feature-table load: non-coherent + L2 cache-hint (evict-last policy)
__device__ __forceinline__ float4 ldg_keep(const float4* p, uint64_t pol) {
    float4 v;
    asm("ld.global.nc.L2::cache_hint.v4.f32 {%0,%1,%2,%3}, [%4], %5;"
        : "=f"(v.x), "=f"(v.y), "=f"(v.z), "=f"(v.w) : "l"(p), "l"(pol));
    return v;
}

// streaming int load (read-once index arrays)
__device__ __forceinline__ int ldg_stream(const int* p) {
    int v;
    asm("ld.global.cs.s32 %0, [%1];" : "=r"(v) : "l"(p));
    return v;
}

// streaming store (don't pollute L2 with output)
__device__ __forceinline__ void stg_stream(float4* p, float4 v) {
    asm volatile("st.global.cs.v4.f32 [%0], {%1,%2,%3,%4};"
                 :: "l"(p), "f"(v.x), "f"(v.y), "f"(v.z), "f"(v.w));
}

__device__ __forceinline__ void mma_tf32(float* d,
                                         uint32_t a0, uint32_t a1,
                                         uint32_t a2, uint32_t a3,
                                         uint32_t b0, uint32_t b1)
{
    asm("mma.sync.aligned.m16n8k8.row.col.f32.tf32.tf32.f32 "
        "{%0,%1,%2,%3}, {%4,%5,%6,%7}, {%8,%9}, {%0,%1,%2,%3};"
        : "+f"(d[0]), "+f"(d[1]), "+f"(d[2]), "+f"(d[3])
        : "r"(a0), "r"(a1), "r"(a2), "r"(a3), "r"(b0), "r"(b1));
}

__global__ __launch_bounds__(THREADS, 2)
void gsage_tc_kernel(const int*   __restrict__ node_idx,
                     const int*   __restrict__ neigh_idx,
                     const float* __restrict__ features,
                     const float* __restrict__ W,
                     const float* __restrict__ b,
                     float*       __restrict__ out,
                     int n_nodes, int n_samp)
{
    extern __shared__ char smem[];
    float*    As   = reinterpret_cast<float*>(smem);               // [32][260]
    int*      idxS = reinterpret_cast<int*>(smem + AS_BYTES);      // gather only
    uint32_t* Ws   = reinterpret_cast<uint32_t*>(smem + AS_BYTES); // gemm only
    float*    invN = reinterpret_cast<float*>(smem + AS_BYTES + R2_BYTES);

    const int tid       = threadIdx.x;
    const int blockBase = blockIdx.x * BM;
    const int rows      = min(BM, n_nodes - blockBase);
    const int S         = n_samp + 1;

    // ---- stage indices: slot 0 = self, slots 1..n_samp = neighbors ----
    for (int i = tid; i < rows * S; i += THREADS) {
        int n = i / S, s = i - n * S;
        int gn = blockBase + n;
        idxS[n * S + s] = (s == 0) ? ldg_stream(node_idx + gn)
                                   : ldg_stream(neigh_idx + (long)gn * n_samp + (s - 1));
    }
    __syncthreads();

    // ---- gather + mean: float4 columns, 4 nodes per thread; tf32 store ----
    {
        const uint64_t pol = mk_keep_policy();
        const int c4 = tid & 63;
        const int n0 = (tid >> 6) * 4;
        const float4* F4 = reinterpret_cast<const float4*>(features);

        const bool v0 = (n0 + 0) < rows;
        const bool v1 = (n0 + 1) < rows;
        const bool v2 = (n0 + 2) < rows;
        const bool v3 = (n0 + 3) < rows;
        const int* ip0 = idxS + (v0 ? (n0 + 0) * S : 0);
        const int* ip1 = idxS + (v1 ? (n0 + 1) * S : 0);
        const int* ip2 = idxS + (v2 ? (n0 + 2) * S : 0);
        const int* ip3 = idxS + (v3 ? (n0 + 3) * S : 0);

        float4 a0 = {0,0,0,0}, a1 = {0,0,0,0}, a2 = {0,0,0,0}, a3 = {0,0,0,0};

        #pragma unroll 4
        for (int s = 0; s < S; ++s) {
            float4 t0 = ldg_keep(F4 + (long)ip0[s] * (DDIM/4) + c4, pol);
            float4 t1 = ldg_keep(F4 + (long)ip1[s] * (DDIM/4) + c4, pol);
            float4 t2 = ldg_keep(F4 + (long)ip2[s] * (DDIM/4) + c4, pol);
            float4 t3 = ldg_keep(F4 + (long)ip3[s] * (DDIM/4) + c4, pol);
            a0.x += t0.x; a0.y += t0.y; a0.z += t0.z; a0.w += t0.w;
            a1.x += t1.x; a1.y += t1.y; a1.z += t1.z; a1.w += t1.w;
            a2.x += t2.x; a2.y += t2.y; a2.z += t2.z; a2.w += t2.w;
            a3.x += t3.x; a3.y += t3.y; a3.z += t3.z; a3.w += t3.w;
        }

        const float invS = 1.0f / (float)S;
        const float m0 = v0 ? invS : 0.0f, m1 = v1 ? invS : 0.0f;
        const float m2 = v2 ? invS : 0.0f, m3 = v3 ? invS : 0.0f;

        uint4 u0 = { f2tf32(a0.x*m0), f2tf32(a0.y*m0), f2tf32(a0.z*m0), f2tf32(a0.w*m0) };
        uint4 u1 = { f2tf32(a1.x*m1), f2tf32(a1.y*m1), f2tf32(a1.z*m1), f2tf32(a1.w*m1) };
        uint4 u2 = { f2tf32(a2.x*m2), f2tf32(a2.y*m2), f2tf32(a2.z*m2), f2tf32(a2.w*m2) };
        uint4 u3 = { f2tf32(a3.x*m3), f2tf32(a3.y*m3), f2tf32(a3.z*m3), f2tf32(a3.w*m3) };

        *reinterpret_cast<uint4*>(&As[(n0 + 0) * ASTRIDE + 4 * c4]) = u0;
        *reinterpret_cast<uint4*>(&As[(n0 + 1) * ASTRIDE + 4 * c4]) = u1;
        *reinterpret_cast<uint4*>(&As[(n0 + 2) * ASTRIDE + 4 * c4]) = u2;
        *reinterpret_cast<uint4*>(&As[(n0 + 3) * ASTRIDE + 4 * c4]) = u3;
    }
    __syncthreads();   // As ready; idxS dead -> Ws region live

    // ---- tensor-core GEMM: tf32 m16n8k8, W staged via smem ----
    const int lane = tid & 31, warp = tid >> 5;
    const int g    = lane >> 2, t = lane & 3;
    const int mrow  = (warp & 1) * 16;
    const int nbase = (warp >> 1) * 32;

    const int kk = tid >> 6;
    const int n4 = (tid & 63) * 4;

    float d[4][4];
    #pragma unroll
    for (int j = 0; j < 4; ++j)
        #pragma unroll
        for (int c = 0; c < 4; ++c) d[j][c] = 0.0f;

    const uint32_t* a_lo = reinterpret_cast<const uint32_t*>(As) + (mrow + g) * ASTRIDE;
    const uint32_t* a_hi = a_lo + 8 * ASTRIDE;

    {
        float4 w = *reinterpret_cast<const float4*>(&W[kk * DDIM + n4]);
        uint4 u = { f2tf32(w.x), f2tf32(w.y), f2tf32(w.z), f2tf32(w.w) };
        *reinterpret_cast<uint4*>(&Ws[kk * WSTRIDE + n4]) = u;
    }
    __syncthreads();

    for (int kc = 0; kc < DDIM / 8; ++kc) {
        const uint32_t* Wb = Ws + (kc & 1) * (8 * WSTRIDE);

        if (kc + 1 < DDIM / 8) {
            float4 w = *reinterpret_cast<const float4*>(
                           &W[((kc + 1) * 8 + kk) * DDIM + n4]);
            uint4 u = { f2tf32(w.x), f2tf32(w.y), f2tf32(w.z), f2tf32(w.w) };
            *reinterpret_cast<uint4*>(
                &Ws[((kc + 1) & 1) * (8 * WSTRIDE) + kk * WSTRIDE + n4]) = u;
        }

        const int k0 = kc * 8;
        uint32_t fa0 = a_lo[k0 + t];
        uint32_t fa1 = a_hi[k0 + t];
        uint32_t fa2 = a_lo[k0 + t + 4];
        uint32_t fa3 = a_hi[k0 + t + 4];

        #pragma unroll
        for (int j = 0; j < 4; ++j) {
            int n = nbase + 8 * j + g;
            uint32_t b0 = Wb[t * WSTRIDE + n];
            uint32_t b1 = Wb[(t + 4) * WSTRIDE + n];
            mma_tf32(d[j], fa0, fa1, fa2, fa3, b0, b1);
        }
        __syncthreads();
    }

    // ---- epilogue: bias + relu into smem (overwrite As) ----
    #pragma unroll
    for (int j = 0; j < 4; ++j) {
        int col = nbase + 8 * j + 2 * t;
        float2 bb = __ldg(reinterpret_cast<const float2*>(b + col));
        float2 lo, hi;
        lo.x = fmaxf(d[j][0] + bb.x, 0.0f);
        lo.y = fmaxf(d[j][1] + bb.y, 0.0f);
        hi.x = fmaxf(d[j][2] + bb.x, 0.0f);
        hi.y = fmaxf(d[j][3] + bb.y, 0.0f);
        *reinterpret_cast<float2*>(&As[(mrow + g)     * ASTRIDE + col]) = lo;
        *reinterpret_cast<float2*>(&As[(mrow + g + 8) * ASTRIDE + col]) = hi;
    }
    __syncthreads();

    // ---- per-row L2 norm: warp w handles rows 2w, 2w+1 ----
    #pragma unroll
    for (int rr = 0; rr < 2; ++rr) {
        int row = warp * 2 + rr;
        float s = 0.0f;
        #pragma unroll
        for (int jj = 0; jj < 8; ++jj) {
            float v = As[row * ASTRIDE + lane + 32 * jj];
            s = fmaf(v, v, s);
        }
        #pragma unroll
        for (int o = 16; o > 0; o >>= 1)
            s += __shfl_xor_sync(0xffffffffu, s, o);
        if (lane == 0)
            invN[row] = 1.0f / fmaxf(sqrtf(s), 1e-12f);
    }
    __syncthreads();

    // ---- normalized streaming store ----
    float4* out4 = reinterpret_cast<float4*>(out);
    for (int i = tid; i < BM * (DDIM / 4); i += THREADS) {
        int r = i >> 6, c = i & 63;
        if (r < rows) {
            float4 v = *reinterpret_cast<const float4*>(&As[r * ASTRIDE + 4 * c]);
            float sc = invN[r];
            v.x *= sc; v.y *= sc; v.z *= sc; v.w *= sc;
            stg_stream(out4 + (long)(blockBase + r) * (DDIM / 4) + c, v);
        }
    }
}

extern "C" void kernel_launch(void* const* d_in, const int* in_sizes, int n_in,
                              void* d_out, int out_size)
{
    const int*   node_idx  = (const int*)  d_in[0];
    const int*   neigh_idx = (const int*)  d_in[1];
    const float* features  = (const float*)d_in[2];
    const float* W         = (const float*)d_in[3];
    const float* b         = (const float*)d_in[4];
    float*       out       = (float*)      d_out;

    const int n_nodes = in_sizes[0];
    const int n_samp  = in_sizes[1] / n_nodes;   // 32

    cudaFuncSetAttribute(gsage_tc_kernel,
                         cudaFuncAttributeMaxDynamicSharedMemorySize, SMEM_BYTES);

    const int grid = (n_nodes + BM - 1) / BM;
    gsage_tc_kernel<<<grid, THREADS, SMEM_BYTES>>>(node_idx, neigh_idx,
                                                   features, W, b, out,
                                                   n_nodes, n_samp);
}

// round 9
// speedup vs baseline: 1.2796x; 1.2796x over previous
#include <cuda_runtime.h>
#include <cuda_bf16.h>
#include <cuda_fp16.h>
#include <cstdint>

// Fused GraphSAGE layer, two kernels:
//  K1: convert feature table fp32 -> fp16 into static __device__ scratch
//      (fp16 table ~102MB fits in the 126MB L2; writes warm L2).
//  K2: gather (fp16, one warp = full 512B row per LDG sweep) + mean,
//      tf32 mma.sync m16n8k8 GEMM (W staged via smem), bias/relu,
//      shuffle row L2-norm, streaming store.

#define BM      32
#define DDIM    256
#define THREADS 512
#define MAX_S   40
#define ASTRIDE 260     // A tile row stride (words)
#define WSTRIDE 264     // W chunk row stride (words)
#define NTAB_CAP 200000 // fp16 table capacity (rows)

#define AS_BYTES  (BM * ASTRIDE * 4)
#define WS_BYTES  (2 * 8 * WSTRIDE * 4)
#define IDX_BYTES (BM * MAX_S * 4)
#define R2_BYTES  (WS_BYTES > IDX_BYTES ? WS_BYTES : IDX_BYTES)
#define SMEM_BYTES (AS_BYTES + R2_BYTES + 128)

// fp16 feature table: 200000 rows x 256 cols x 2B = 102.4 MB, 32 uint4/row
__device__ uint4 g_feat16[(size_t)NTAB_CAP * 32];

__device__ __forceinline__ uint32_t f2tf32(float f) {
    uint32_t u;
    asm("cvt.rna.tf32.f32 %0, %1;" : "=r"(u) : "f"(f));
    return u;
}

__device__ __forceinline__ int ldg_stream(const int* p) {
    int v;
    asm("ld.global.cs.s32 %0, [%1];" : "=r"(v) : "l"(p));
    return v;
}

__device__ __forceinline__ float4 ldg_stream4(const float4* p) {
    float4 v;
    asm("ld.global.cs.v4.f32 {%0,%1,%2,%3}, [%4];"
        : "=f"(v.x), "=f"(v.y), "=f"(v.z), "=f"(v.w) : "l"(p));
    return v;
}

__device__ __forceinline__ void stg_stream(float4* p, float4 v) {
    asm volatile("st.global.cs.v4.f32 [%0], {%1,%2,%3,%4};"
                 :: "l"(p), "f"(v.x), "f"(v.y), "f"(v.z), "f"(v.w));
}

__device__ __forceinline__ void mma_tf32(float* d,
                                         uint32_t a0, uint32_t a1,
                                         uint32_t a2, uint32_t a3,
                                         uint32_t b0, uint32_t b1)
{
    asm("mma.sync.aligned.m16n8k8.row.col.f32.tf32.tf32.f32 "
        "{%0,%1,%2,%3}, {%4,%5,%6,%7}, {%8,%9}, {%0,%1,%2,%3};"
        : "+f"(d[0]), "+f"(d[1]), "+f"(d[2]), "+f"(d[3])
        : "r"(a0), "r"(a1), "r"(a2), "r"(a3), "r"(b0), "r"(b1));
}

// ---- K1: fp32 -> fp16 table conversion ----
__global__ void cvt_f16_kernel(const float4* __restrict__ F4, int n_vec)
{
    int i      = blockIdx.x * blockDim.x + threadIdx.x;
    int stride = gridDim.x * blockDim.x;
    for (; i < n_vec; i += stride) {
        float4 f0 = ldg_stream4(F4 + 2 * (long)i);
        float4 f1 = ldg_stream4(F4 + 2 * (long)i + 1);
        __half2 h0 = __float22half2_rn(make_float2(f0.x, f0.y));
        __half2 h1 = __float22half2_rn(make_float2(f0.z, f0.w));
        __half2 h2 = __float22half2_rn(make_float2(f1.x, f1.y));
        __half2 h3 = __float22half2_rn(make_float2(f1.z, f1.w));
        uint4 u;
        u.x = *reinterpret_cast<uint32_t*>(&h0);
        u.y = *reinterpret_cast<uint32_t*>(&h1);
        u.z = *reinterpret_cast<uint32_t*>(&h2);
        u.w = *reinterpret_cast<uint32_t*>(&h3);
        g_feat16[i] = u;   // default .wb: warms L2 with the fp16 table
    }
}

// ---- K2: gather + GEMM + epilogue ----
template<bool USE_F16>
__global__ __launch_bounds__(THREADS, 2)
void gsage_tc_kernel(const int*   __restrict__ node_idx,
                     const int*   __restrict__ neigh_idx,
                     const float* __restrict__ features,
                     const float* __restrict__ W,
                     const float* __restrict__ b,
                     float*       __restrict__ out,
                     int n_nodes, int n_samp)
{
    extern __shared__ char smem[];
    float*    As   = reinterpret_cast<float*>(smem);               // [32][260]
    int*      idxS = reinterpret_cast<int*>(smem + AS_BYTES);      // gather only
    uint32_t* Ws   = reinterpret_cast<uint32_t*>(smem + AS_BYTES); // gemm only
    float*    invN = reinterpret_cast<float*>(smem + AS_BYTES + R2_BYTES);

    const int tid       = threadIdx.x;
    const int blockBase = blockIdx.x * BM;
    const int rows      = min(BM, n_nodes - blockBase);
    const int S         = n_samp + 1;

    // ---- stage indices: slot 0 = self, slots 1..n_samp = neighbors ----
    for (int i = tid; i < rows * S; i += THREADS) {
        int n = i / S, s = i - n * S;
        int gn = blockBase + n;
        idxS[n * S + s] = (s == 0) ? ldg_stream(node_idx + gn)
                                   : ldg_stream(neigh_idx + (long)gn * n_samp + (s - 1));
    }
    __syncthreads();

    const float invS = 1.0f / (float)S;

    if (USE_F16) {
        // ---- fp16 gather: warp w -> nodes 2w,2w+1; lane -> cols 8l..8l+7 ----
        const int lane = tid & 31;
        const int w    = tid >> 5;
        const int n0 = 2 * w, n1 = 2 * w + 1;
        const bool v0 = n0 < rows, v1 = n1 < rows;
        const int* ip0 = idxS + (v0 ? n0 * S : 0);
        const int* ip1 = idxS + (v1 ? n1 * S : 0);

        float acc0[8], acc1[8];
        #pragma unroll
        for (int j = 0; j < 8; ++j) { acc0[j] = 0.0f; acc1[j] = 0.0f; }

        #pragma unroll 4
        for (int s = 0; s < S; ++s) {
            uint4 u0 = g_feat16[(long)ip0[s] * 32 + lane];
            uint4 u1 = g_feat16[(long)ip1[s] * 32 + lane];
            const __half2* h0 = reinterpret_cast<const __half2*>(&u0);
            const __half2* h1 = reinterpret_cast<const __half2*>(&u1);
            #pragma unroll
            for (int j = 0; j < 4; ++j) {
                float2 f0 = __half22float2(h0[j]);
                float2 f1 = __half22float2(h1[j]);
                acc0[2*j]   += f0.x; acc0[2*j+1] += f0.y;
                acc1[2*j]   += f1.x; acc1[2*j+1] += f1.y;
            }
        }

        const float m0 = v0 ? invS : 0.0f, m1 = v1 ? invS : 0.0f;
        uint4 o0a, o0b, o1a, o1b;
        o0a.x = f2tf32(acc0[0]*m0); o0a.y = f2tf32(acc0[1]*m0);
        o0a.z = f2tf32(acc0[2]*m0); o0a.w = f2tf32(acc0[3]*m0);
        o0b.x = f2tf32(acc0[4]*m0); o0b.y = f2tf32(acc0[5]*m0);
        o0b.z = f2tf32(acc0[6]*m0); o0b.w = f2tf32(acc0[7]*m0);
        o1a.x = f2tf32(acc1[0]*m1); o1a.y = f2tf32(acc1[1]*m1);
        o1a.z = f2tf32(acc1[2]*m1); o1a.w = f2tf32(acc1[3]*m1);
        o1b.x = f2tf32(acc1[4]*m1); o1b.y = f2tf32(acc1[5]*m1);
        o1b.z = f2tf32(acc1[6]*m1); o1b.w = f2tf32(acc1[7]*m1);
        *reinterpret_cast<uint4*>(&As[n0 * ASTRIDE + 8 * lane])     = o0a;
        *reinterpret_cast<uint4*>(&As[n0 * ASTRIDE + 8 * lane + 4]) = o0b;
        *reinterpret_cast<uint4*>(&As[n1 * ASTRIDE + 8 * lane])     = o1a;
        *reinterpret_cast<uint4*>(&As[n1 * ASTRIDE + 8 * lane + 4]) = o1b;
    } else {
        // ---- fp32 fallback gather (R6 path) ----
        const int c4 = tid & 63;
        const int n0 = (tid >> 6) * 4;
        const float4* F4 = reinterpret_cast<const float4*>(features);

        const bool v0 = (n0 + 0) < rows, v1 = (n0 + 1) < rows;
        const bool v2 = (n0 + 2) < rows, v3 = (n0 + 3) < rows;
        const int* ip0 = idxS + (v0 ? (n0 + 0) * S : 0);
        const int* ip1 = idxS + (v1 ? (n0 + 1) * S : 0);
        const int* ip2 = idxS + (v2 ? (n0 + 2) * S : 0);
        const int* ip3 = idxS + (v3 ? (n0 + 3) * S : 0);

        float4 a0 = {0,0,0,0}, a1 = {0,0,0,0}, a2 = {0,0,0,0}, a3 = {0,0,0,0};
        #pragma unroll 4
        for (int s = 0; s < S; ++s) {
            float4 t0 = __ldg(F4 + (long)ip0[s] * (DDIM/4) + c4);
            float4 t1 = __ldg(F4 + (long)ip1[s] * (DDIM/4) + c4);
            float4 t2 = __ldg(F4 + (long)ip2[s] * (DDIM/4) + c4);
            float4 t3 = __ldg(F4 + (long)ip3[s] * (DDIM/4) + c4);
            a0.x += t0.x; a0.y += t0.y; a0.z += t0.z; a0.w += t0.w;
            a1.x += t1.x; a1.y += t1.y; a1.z += t1.z; a1.w += t1.w;
            a2.x += t2.x; a2.y += t2.y; a2.z += t2.z; a2.w += t2.w;
            a3.x += t3.x; a3.y += t3.y; a3.z += t3.z; a3.w += t3.w;
        }
        const float m0 = v0 ? invS : 0.0f, m1 = v1 ? invS : 0.0f;
        const float m2 = v2 ? invS : 0.0f, m3 = v3 ? invS : 0.0f;
        uint4 u0 = { f2tf32(a0.x*m0), f2tf32(a0.y*m0), f2tf32(a0.z*m0), f2tf32(a0.w*m0) };
        uint4 u1 = { f2tf32(a1.x*m1), f2tf32(a1.y*m1), f2tf32(a1.z*m1), f2tf32(a1.w*m1) };
        uint4 u2 = { f2tf32(a2.x*m2), f2tf32(a2.y*m2), f2tf32(a2.z*m2), f2tf32(a2.w*m2) };
        uint4 u3 = { f2tf32(a3.x*m3), f2tf32(a3.y*m3), f2tf32(a3.z*m3), f2tf32(a3.w*m3) };
        *reinterpret_cast<uint4*>(&As[(n0 + 0) * ASTRIDE + 4 * c4]) = u0;
        *reinterpret_cast<uint4*>(&As[(n0 + 1) * ASTRIDE + 4 * c4]) = u1;
        *reinterpret_cast<uint4*>(&As[(n0 + 2) * ASTRIDE + 4 * c4]) = u2;
        *reinterpret_cast<uint4*>(&As[(n0 + 3) * ASTRIDE + 4 * c4]) = u3;
    }
    __syncthreads();   // As ready; idxS dead -> Ws region live

    // ---- tensor-core GEMM: tf32 m16n8k8, W staged via smem ----
    const int lane = tid & 31, warp = tid >> 5;
    const int g    = lane >> 2, t = lane & 3;
    const int mrow  = (warp & 1) * 16;
    const int nbase = (warp >> 1) * 32;

    const int kk = tid >> 6;
    const int n4 = (tid & 63) * 4;

    float d[4][4];
    #pragma unroll
    for (int j = 0; j < 4; ++j)
        #pragma unroll
        for (int c = 0; c < 4; ++c) d[j][c] = 0.0f;

    const uint32_t* a_lo = reinterpret_cast<const uint32_t*>(As) + (mrow + g) * ASTRIDE;
    const uint32_t* a_hi = a_lo + 8 * ASTRIDE;

    {
        float4 w = *reinterpret_cast<const float4*>(&W[kk * DDIM + n4]);
        uint4 u = { f2tf32(w.x), f2tf32(w.y), f2tf32(w.z), f2tf32(w.w) };
        *reinterpret_cast<uint4*>(&Ws[kk * WSTRIDE + n4]) = u;
    }
    __syncthreads();

    for (int kc = 0; kc < DDIM / 8; ++kc) {
        const uint32_t* Wb = Ws + (kc & 1) * (8 * WSTRIDE);

        if (kc + 1 < DDIM / 8) {
            float4 w = *reinterpret_cast<const float4*>(
                           &W[((kc + 1) * 8 + kk) * DDIM + n4]);
            uint4 u = { f2tf32(w.x), f2tf32(w.y), f2tf32(w.z), f2tf32(w.w) };
            *reinterpret_cast<uint4*>(
                &Ws[((kc + 1) & 1) * (8 * WSTRIDE) + kk * WSTRIDE + n4]) = u;
        }

        const int k0 = kc * 8;
        uint32_t fa0 = a_lo[k0 + t];
        uint32_t fa1 = a_hi[k0 + t];
        uint32_t fa2 = a_lo[k0 + t + 4];
        uint32_t fa3 = a_hi[k0 + t + 4];

        #pragma unroll
        for (int j = 0; j < 4; ++j) {
            int n = nbase + 8 * j + g;
            uint32_t b0 = Wb[t * WSTRIDE + n];
            uint32_t b1 = Wb[(t + 4) * WSTRIDE + n];
            mma_tf32(d[j], fa0, fa1, fa2, fa3, b0, b1);
        }
        __syncthreads();
    }

    // ---- epilogue: bias + relu into smem (overwrite As) ----
    #pragma unroll
    for (int j = 0; j < 4; ++j) {
        int col = nbase + 8 * j + 2 * t;
        float2 bb = __ldg(reinterpret_cast<const float2*>(b + col));
        float2 lo, hi;
        lo.x = fmaxf(d[j][0] + bb.x, 0.0f);
        lo.y = fmaxf(d[j][1] + bb.y, 0.0f);
        hi.x = fmaxf(d[j][2] + bb.x, 0.0f);
        hi.y = fmaxf(d[j][3] + bb.y, 0.0f);
        *reinterpret_cast<float2*>(&As[(mrow + g)     * ASTRIDE + col]) = lo;
        *reinterpret_cast<float2*>(&As[(mrow + g + 8) * ASTRIDE + col]) = hi;
    }
    __syncthreads();

    // ---- per-row L2 norm: warp w handles rows 2w, 2w+1 ----
    #pragma unroll
    for (int rr = 0; rr < 2; ++rr) {
        int row = warp * 2 + rr;
        float s = 0.0f;
        #pragma unroll
        for (int jj = 0; jj < 8; ++jj) {
            float v = As[row * ASTRIDE + lane + 32 * jj];
            s = fmaf(v, v, s);
        }
        #pragma unroll
        for (int o = 16; o > 0; o >>= 1)
            s += __shfl_xor_sync(0xffffffffu, s, o);
        if (lane == 0)
            invN[row] = 1.0f / fmaxf(sqrtf(s), 1e-12f);
    }
    __syncthreads();

    // ---- normalized streaming store ----
    float4* out4 = reinterpret_cast<float4*>(out);
    for (int i = tid; i < BM * (DDIM / 4); i += THREADS) {
        int r = i >> 6, c = i & 63;
        if (r < rows) {
            float4 v = *reinterpret_cast<const float4*>(&As[r * ASTRIDE + 4 * c]);
            float sc = invN[r];
            v.x *= sc; v.y *= sc; v.z *= sc; v.w *= sc;
            stg_stream(out4 + (long)(blockBase + r) * (DDIM / 4) + c, v);
        }
    }
}

extern "C" void kernel_launch(void* const* d_in, const int* in_sizes, int n_in,
                              void* d_out, int out_size)
{
    const int*   node_idx  = (const int*)  d_in[0];
    const int*   neigh_idx = (const int*)  d_in[1];
    const float* features  = (const float*)d_in[2];
    const float* W         = (const float*)d_in[3];
    const float* b         = (const float*)d_in[4];
    float*       out       = (float*)      d_out;

    const int n_nodes = in_sizes[0];
    const int n_samp  = in_sizes[1] / n_nodes;   // 32
    const int n_table = in_sizes[2] / DDIM;
    const int grid    = (n_nodes + BM - 1) / BM;

    if (n_table <= NTAB_CAP) {
        // K1: convert table to fp16 (warms L2 with the fp16 table)
        const int n_vec = n_table * 32;            // uint4 outputs
        cvt_f16_kernel<<<3125, 512>>>(
            reinterpret_cast<const float4*>(features), n_vec);

        cudaFuncSetAttribute(gsage_tc_kernel<true>,
                             cudaFuncAttributeMaxDynamicSharedMemorySize, SMEM_BYTES);
        gsage_tc_kernel<true><<<grid, THREADS, SMEM_BYTES>>>(
            node_idx, neigh_idx, features, W, b, out, n_nodes, n_samp);
    } else {
        cudaFuncSetAttribute(gsage_tc_kernel<false>,
                             cudaFuncAttributeMaxDynamicSharedMemorySize, SMEM_BYTES);
        gsage_tc_kernel<false><<<grid, THREADS, SMEM_BYTES>>>(
            node_idx, neigh_idx, features, W, b, out, n_nodes, n_samp);
    }
}